// round 10
// baseline (speedup 1.0000x reference)
#include <cuda_runtime.h>
#include <cuda_fp16.h>
#include <math.h>

// PixelCNN fused forward — both convs on tensor cores (m16n8k16 fp16/fp32,
// 3-term hi/lo split everywhere).
// conv1: X2[m][16] = [xhi(8 kx-window) | xlo(8)], ky taps = row shifts of 66.
//        B1main = [Wh;Wh] (dup k-halves -> xhi*Wh + xlo*Wh in 1 MMA),
//        B1low  = [Wl;0]  (-> xhi*Wl).
// conv2: A2[m][32] = [h1hi(16ic) | h1lo(16ic)], 5 taps = shifts {0,1,2,66,67}.
// Stripe TH=4 rows/block, dynamic smem 55.5KB, 4 CTAs/SM.

#define IMG_H 64
#define IMG_W 64
#define NCH   16
#define TH    4
#define XR    (TH + 4)     // 8 x-halo rows
#define XC    (IMG_W + 8)  // 72
#define X2ROWS 544         // 8*66=528 used + 16 pad
#define A2ROWS 416         // 5*66=330 used, reads to 402, pad to 416

// dynamic smem layout (bytes)
#define SX_OFF   0                      // 8*72*4      = 2304
#define X2_OFF   2304                   // 544*16*2    = 17408
#define A2_OFF   (X2_OFF + 17408)       // 19712; 416*32*2 = 26624
#define B1M_OFF  (A2_OFF + 26624)       // 46336; 4*16*16*2 = 2048
#define B1L_OFF  (B1M_OFF + 2048)       // 48384
#define B2H_OFF  (B1L_OFF + 2048)       // 50432; 5*16*16*2 = 2560
#define B2L_OFF  (B2H_OFF + 2560)       // 52992
#define SMEM_TOTAL (B2L_OFF + 2560)     // 55552

struct PackedW {
    float w1t[24][16];    // [tap][oc]
    float w2[16][5][16];  // [ic][tap][oc]
    float b1[16];
    float b2[16];
    float w3[16];
    float b3;
    float pad[3];
};

__device__   PackedW g_w;
__constant__ PackedW c_w;

__device__ __forceinline__ unsigned smem_u32(const void* p) {
    unsigned a;
    asm("{ .reg .u64 t; cvta.to.shared.u64 t, %1; cvt.u32.u64 %0, t; }"
        : "=r"(a) : "l"(p));
    return a;
}
__device__ __forceinline__ void ldsm_x4(unsigned addr, unsigned& r0, unsigned& r1,
                                        unsigned& r2, unsigned& r3) {
    asm volatile("ldmatrix.sync.aligned.m8n8.x4.shared.b16 {%0,%1,%2,%3}, [%4];"
                 : "=r"(r0), "=r"(r1), "=r"(r2), "=r"(r3) : "r"(addr));
}
__device__ __forceinline__ void ldsm_x4t(unsigned addr, unsigned& r0, unsigned& r1,
                                         unsigned& r2, unsigned& r3) {
    asm volatile("ldmatrix.sync.aligned.m8n8.x4.trans.shared.b16 {%0,%1,%2,%3}, [%4];"
                 : "=r"(r0), "=r"(r1), "=r"(r2), "=r"(r3) : "r"(addr));
}
__device__ __forceinline__ void mma16816(float& d0, float& d1, float& d2, float& d3,
                                         unsigned a0, unsigned a1, unsigned a2, unsigned a3,
                                         unsigned b0, unsigned b1) {
    asm volatile(
        "mma.sync.aligned.m16n8k16.row.col.f32.f16.f16.f32 "
        "{%0,%1,%2,%3}, {%4,%5,%6,%7}, {%8,%9}, {%0,%1,%2,%3};"
        : "+f"(d0), "+f"(d1), "+f"(d2), "+f"(d3)
        : "r"(a0), "r"(a1), "r"(a2), "r"(a3), "r"(b0), "r"(b1));
}

// ---- prep: pack masked weights into g_w ----
__global__ void pixelcnn_prep(const float* __restrict__ w1, const float* __restrict__ b1,
                              const float* __restrict__ w2, const float* __restrict__ b2,
                              const float* __restrict__ w3, const float* __restrict__ b3)
{
    float* dst = reinterpret_cast<float*>(&g_w);
    const int tid = threadIdx.x;

    for (int idx = tid; idx < 24 * NCH; idx += 256) {
        int t = idx / NCH, oc = idx % NCH;
        int ky, kx;
        if (t < 21) { ky = t / 7; kx = t % 7; }
        else        { ky = 3;     kx = t - 21; }
        dst[idx] = w1[oc * 49 + ky * 7 + kx];
    }
    for (int idx = tid; idx < NCH * 5 * NCH; idx += 256) {
        int ic  = idx / (5 * NCH);
        int rem = idx % (5 * NCH);
        int t   = rem / NCH;
        int oc  = rem % NCH;
        int ky, kx;
        if (t < 3) { ky = 0; kx = t; }
        else       { ky = 1; kx = t - 3; }
        dst[384 + idx] = w2[((oc * NCH + ic) * 3 + ky) * 3 + kx];
    }
    if (tid < NCH) {
        dst[1664 + tid] = b1[tid];
        dst[1680 + tid] = b2[tid];
        dst[1696 + tid] = w3[tid];
    }
    if (tid == 0) dst[1712] = b3[0];
}

__global__ __launch_bounds__(256, 4)
void pixelcnn_fused(const float* __restrict__ x, float* __restrict__ out)
{
    extern __shared__ __align__(16) char smem_buf[];
    float*  sx  = reinterpret_cast<float*>(smem_buf + SX_OFF);    // [8][72]
    __half* X2  = reinterpret_cast<__half*>(smem_buf + X2_OFF);   // [544][16]
    __half* A2  = reinterpret_cast<__half*>(smem_buf + A2_OFF);   // [416][32]
    __half* B1m = reinterpret_cast<__half*>(smem_buf + B1M_OFF);  // [4][16][16]
    __half* B1l = reinterpret_cast<__half*>(smem_buf + B1L_OFF);  // [4][16][16]
    __half* B2h = reinterpret_cast<__half*>(smem_buf + B2H_OFF);  // [5][16][16]
    __half* B2l = reinterpret_cast<__half*>(smem_buf + B2L_OFF);  // [5][16][16]

    const int tid  = threadIdx.x;
    const int lane = tid & 31;
    const int wid  = tid >> 5;
    const int img  = blockIdx.y;
    const int r0   = blockIdx.x * TH;
    const float* __restrict__ xim = x + img * (IMG_H * IMG_W);
    const float* cwf = reinterpret_cast<const float*>(&c_w);

    // ---- phase 1: x halo tile + B matrices + zero pads ----
    for (int idx = tid; idx < XR * XC; idx += 256) {
        int i = idx / XC, j = idx % XC;
        int gr = r0 - 4 + i;
        int gc = j - 4;
        float v = 0.0f;
        if (gr >= 0 && gr < IMG_H && gc >= 0 && gc < IMG_W)
            v = xim[gr * IMG_W + gc];
        sx[idx] = v;
    }
    // conv1 B: B1m[ky][kr][oc] = Wh (both k-halves); B1l = [Wl ; 0]
    for (int idx = tid; idx < 4 * 16 * 16; idx += 256) {
        int ky = idx >> 8;
        int kr = (idx >> 4) & 15;
        int oc = idx & 15;
        int kx = kr & 7;
        float wv = 0.0f;
        if (kx < 7) {
            if (ky < 3)      wv = cwf[(ky * 7 + kx) * 16 + oc];
            else if (kx < 3) wv = cwf[(21 + kx) * 16 + oc];
        }
        __half hi = __float2half_rn(wv);
        __half lo = __float2half_rn(wv - __half2float(hi));
        B1m[idx] = hi;
        B1l[idx] = (kr < 8) ? lo : __half(0.0f);
    }
    // conv2 B hi/lo
    for (int idx = tid; idx < 16 * 5 * 16; idx += 256) {
        int ic  = idx / 80;
        int rem = idx % 80;
        int t   = rem / 16;
        int oc  = rem % 16;
        float v = cwf[384 + ic * 80 + t * 16 + oc];
        __half hi = __float2half_rn(v);
        __half lo = __float2half_rn(v - __half2float(hi));
        B2h[(t * 16 + ic) * 16 + oc] = hi;
        B2l[(t * 16 + ic) * 16 + oc] = lo;
    }
    // zero X2 pad rows 528..543 (16 rows * 8 u32)
    for (int idx = tid; idx < 128; idx += 256)
        reinterpret_cast<unsigned*>(X2)[528 * 8 + idx] = 0u;
    // zero A2 pad rows 330..415 (86 rows * 16 u32)
    for (int idx = tid; idx < 86 * 16; idx += 256)
        reinterpret_cast<unsigned*>(A2)[330 * 16 + idx] = 0u;
    __syncthreads();

    // ---- phase 2: build X2[m][16] = [xhi(8) | xlo(8)] ----
    for (int m = tid; m < 528; m += 256) {
        const int xr = m / 66;
        const int hc = m - xr * 66;
        unsigned hiw[4], low[4];
        #pragma unroll
        for (int q = 0; q < 4; q++) {
            float v0 = sx[xr * 72 + hc + q * 2];
            float v1 = (q * 2 + 1 < 7) ? sx[xr * 72 + hc + q * 2 + 1] : 0.0f;
            float2 vm = make_float2(v0, v1);
            __half2 hh = __float22half2_rn(vm);
            float2 back = __half22float2(hh);
            __half2 hl = __float22half2_rn(make_float2(vm.x - back.x, vm.y - back.y));
            hiw[q] = *reinterpret_cast<unsigned*>(&hh);
            low[q] = *reinterpret_cast<unsigned*>(&hl);
        }
        uint4* row = reinterpret_cast<uint4*>(X2 + m * 16);
        row[0] = make_uint4(hiw[0], hiw[1], hiw[2], hiw[3]);
        row[1] = make_uint4(low[0], low[1], low[2], low[3]);
    }
    __syncthreads();

    const unsigned x2_b  = smem_u32(X2);
    const unsigned a2_b  = smem_u32(A2);
    const unsigned b1m_b = smem_u32(B1m);
    const unsigned b1l_b = smem_u32(B1l);
    const unsigned b2h_b = smem_u32(B2h);
    const unsigned b2l_b = smem_u32(B2l);

    const unsigned arow  = lane & 15;
    const unsigned akoff = (lane >> 4) * 16;
    const unsigned brow  = lane & 15;
    const unsigned bnoff = (lane >> 4) * 16;
    const int cb = (lane & 3) * 2;
    const int g  = lane >> 2;

    // ---- phase 3: conv1 via MMA -> A2 (fp16 hi/lo) ----
    {
        // hoist B1main fragments (tile-invariant)
        unsigned bm[4][4];
        #pragma unroll
        for (int ky = 0; ky < 4; ky++) {
            const unsigned bbyte = (unsigned)ky * 512 + brow * 32 + bnoff;
            ldsm_x4t(b1m_b + bbyte, bm[ky][0], bm[ky][1], bm[ky][2], bm[ky][3]);
        }
        float b1c[4];
        #pragma unroll
        for (int j = 0; j < 2; j++) {
            b1c[j]     = cwf[1664 + cb + j];
            b1c[2 + j] = cwf[1664 + cb + 8 + j];
        }

        for (int tile = wid; tile < 21; tile += 8) {
            const int m0 = tile * 16;
            float d0[4] = {0.f, 0.f, 0.f, 0.f};
            float d1[4] = {0.f, 0.f, 0.f, 0.f};

            #pragma unroll
            for (int ky = 0; ky < 4; ky++) {
                const unsigned rbyte = (unsigned)(m0 + ky * 66 + arow) * 32 + akoff;
                unsigned a0, a1, a2, a3;
                ldsm_x4(x2_b + rbyte, a0, a1, a2, a3);
                unsigned l0, l1, l2, l3;
                ldsm_x4t(b1l_b + (unsigned)ky * 512 + brow * 32 + bnoff, l0, l1, l2, l3);

                mma16816(d0[0], d0[1], d0[2], d0[3], a0, a1, a2, a3, bm[ky][0], bm[ky][1]);
                mma16816(d1[0], d1[1], d1[2], d1[3], a0, a1, a2, a3, bm[ky][2], bm[ky][3]);
                mma16816(d0[0], d0[1], d0[2], d0[3], a0, a1, a2, a3, l0, l1);
                mma16816(d1[0], d1[1], d1[2], d1[3], a0, a1, a2, a3, l2, l3);
            }

            // epilogue: +b1, relu, mask, fp16 hi/lo split -> A2
            #pragma unroll
            for (int s = 0; s < 2; s++) {
                const int m  = m0 + g + s * 8;
                const int hr = m / 66;
                const int hc = m - hr * 66;
                const bool ok = (hc >= 1) && (hc <= 64) && (r0 - 1 + hr >= 0) && (hr <= 4);
                float v0 = (s == 0 ? d0[0] : d0[2]) + b1c[0];
                float v1 = (s == 0 ? d0[1] : d0[3]) + b1c[1];
                float v2 = (s == 0 ? d1[0] : d1[2]) + b1c[2];
                float v3 = (s == 0 ? d1[1] : d1[3]) + b1c[3];
                v0 = ok ? fmaxf(v0, 0.f) : 0.f;
                v1 = ok ? fmaxf(v1, 0.f) : 0.f;
                v2 = ok ? fmaxf(v2, 0.f) : 0.f;
                v3 = ok ? fmaxf(v3, 0.f) : 0.f;

                float2 pA = make_float2(v0, v1), pB = make_float2(v2, v3);
                __half2 hA = __float22half2_rn(pA);
                __half2 hB = __float22half2_rn(pB);
                float2 bA = __half22float2(hA), bB = __half22float2(hB);
                __half2 lA = __float22half2_rn(make_float2(pA.x - bA.x, pA.y - bA.y));
                __half2 lB = __float22half2_rn(make_float2(pB.x - bB.x, pB.y - bB.y));

                *reinterpret_cast<unsigned*>(&A2[m * 32 + cb])          = *reinterpret_cast<unsigned*>(&hA);
                *reinterpret_cast<unsigned*>(&A2[m * 32 + cb + 8])      = *reinterpret_cast<unsigned*>(&hB);
                *reinterpret_cast<unsigned*>(&A2[m * 32 + 16 + cb])     = *reinterpret_cast<unsigned*>(&lA);
                *reinterpret_cast<unsigned*>(&A2[m * 32 + 16 + cb + 8]) = *reinterpret_cast<unsigned*>(&lB);
            }
        }
    }
    __syncthreads();

    // ---- phase 4: conv2 via MMA + conv3 + sigmoid ----
    {
        // hoist B2h fragments only (B2l re-loaded per tile)
        unsigned bh[5][4];
        #pragma unroll
        for (int t = 0; t < 5; t++) {
            const unsigned bbyte = (unsigned)t * 512 + brow * 32 + bnoff;
            ldsm_x4t(b2h_b + bbyte, bh[t][0], bh[t][1], bh[t][2], bh[t][3]);
        }
        float b2c[4], w3c[4];
        #pragma unroll
        for (int j = 0; j < 2; j++) {
            b2c[j]     = cwf[1680 + cb + j];
            b2c[2 + j] = cwf[1680 + cb + 8 + j];
            w3c[j]     = cwf[1696 + cb + j];
            w3c[2 + j] = cwf[1696 + cb + 8 + j];
        }
        const float b3v = cwf[1712];
        const int shifts[5] = {0, 1, 2, 66, 67};

        for (int tile = wid; tile < 21; tile += 8) {
            const int m0 = tile * 16;
            float d0[4] = {0.f, 0.f, 0.f, 0.f};
            float d1[4] = {0.f, 0.f, 0.f, 0.f};

            #pragma unroll
            for (int t = 0; t < 5; t++) {
                const unsigned rbyte = (unsigned)(m0 + shifts[t] + arow) * 64 + akoff;
                unsigned ah0, ah1, ah2, ah3, al0, al1, al2, al3;
                ldsm_x4(a2_b + rbyte, ah0, ah1, ah2, ah3);        // hi halves (cols 0..15)
                ldsm_x4(a2_b + rbyte + 32, al0, al1, al2, al3);   // lo halves (cols 16..31)
                unsigned bl0, bl1, bl2, bl3;
                ldsm_x4t(b2l_b + (unsigned)t * 512 + brow * 32 + bnoff, bl0, bl1, bl2, bl3);

                mma16816(d0[0], d0[1], d0[2], d0[3], ah0, ah1, ah2, ah3, bh[t][0], bh[t][1]);
                mma16816(d1[0], d1[1], d1[2], d1[3], ah0, ah1, ah2, ah3, bh[t][2], bh[t][3]);
                mma16816(d0[0], d0[1], d0[2], d0[3], ah0, ah1, ah2, ah3, bl0, bl1);
                mma16816(d1[0], d1[1], d1[2], d1[3], ah0, ah1, ah2, ah3, bl2, bl3);
                mma16816(d0[0], d0[1], d0[2], d0[3], al0, al1, al2, al3, bh[t][0], bh[t][1]);
                mma16816(d1[0], d1[1], d1[2], d1[3], al0, al1, al2, al3, bh[t][2], bh[t][3]);
            }

            float zA = 0.f, zB = 0.f;
            #pragma unroll
            for (int j = 0; j < 2; j++) {
                zA += fmaxf(d0[j]     + b2c[j],     0.0f) * w3c[j];
                zA += fmaxf(d1[j]     + b2c[2 + j], 0.0f) * w3c[2 + j];
                zB += fmaxf(d0[2 + j] + b2c[j],     0.0f) * w3c[j];
                zB += fmaxf(d1[2 + j] + b2c[2 + j], 0.0f) * w3c[2 + j];
            }
            zA += __shfl_xor_sync(0xffffffffu, zA, 1);
            zA += __shfl_xor_sync(0xffffffffu, zA, 2);
            zB += __shfl_xor_sync(0xffffffffu, zB, 1);
            zB += __shfl_xor_sync(0xffffffffu, zB, 2);

            if ((lane & 3) == 0) {
                #pragma unroll
                for (int s = 0; s < 2; s++) {
                    const int m = m0 + g + s * 8;
                    const float z = (s == 0 ? zA : zB) + b3v;
                    const int r = m / 66;
                    const int c = m - r * 66;
                    if (c < 64 && r < TH) {
                        float y = 1.0f / (1.0f + __expf(-z));
                        out[img * (IMG_H * IMG_W) + (r0 + r) * IMG_W + c] = y;
                    }
                }
            }
        }
    }
}

extern "C" void kernel_launch(void* const* d_in, const int* in_sizes, int n_in,
                              void* d_out, int out_size) {
    const float* x  = (const float*)d_in[0];
    const float* w1 = (const float*)d_in[1];
    const float* b1 = (const float*)d_in[2];
    const float* w2 = (const float*)d_in[3];
    const float* b2 = (const float*)d_in[4];
    const float* w3 = (const float*)d_in[5];
    const float* b3 = (const float*)d_in[6];
    float* out = (float*)d_out;

    cudaFuncSetAttribute(pixelcnn_fused,
                         cudaFuncAttributeMaxDynamicSharedMemorySize, SMEM_TOTAL);
    cudaFuncSetAttribute(pixelcnn_fused,
                         cudaFuncAttributePreferredSharedMemoryCarveout, 100);

    pixelcnn_prep<<<1, 256>>>(w1, b1, w2, b2, w3, b3);

    void* g_addr = nullptr;
    cudaGetSymbolAddress(&g_addr, g_w);
    cudaMemcpyToSymbolAsync(c_w, g_addr, sizeof(PackedW), 0,
                            cudaMemcpyDeviceToDevice, 0);

    dim3 grid(IMG_H / TH, 1024);  // (16, 1024)
    pixelcnn_fused<<<grid, 256, SMEM_TOTAL>>>(x, out);
}

// round 11
// speedup vs baseline: 2.1914x; 2.1914x over previous
#include <cuda_runtime.h>
#include <cuda_fp16.h>
#include <math.h>

// PixelCNN fused forward.
// R11 = R9 + XOR bank-swizzle on Ahi/Alo (kills the 2-way ldsm conflicts):
//   physical 16B-chunk = logical chunk ^ ((row>>2)&1).
// conv1 scalar FFMA2 on all 256 threads; conv2+conv3 via mma.m16n8k16,
// hoisted B fragments, 3-term hi/lo split.

#define IMG_H 64
#define IMG_W 64
#define NCH   16
#define TH    8
#define XR    (TH + 4)
#define XC    (IMG_W + 8)
#define AROWS 596          // 9*66 = 594 used + 2 pad

typedef unsigned long long u64;

struct PackedW {
    ulonglong2 w1t[24][4];    // [tap][ocgroup] fp32 pairs
    ulonglong2 w2[16][5][4];  // [ic][tap][ocgroup] fp32
    u64   b1[8];
    u64   b2[8];
    float w3[16];
    float b3;
    float pad[3];
};

__device__   PackedW g_w;
__constant__ PackedW c_w;

__device__ __forceinline__ u64 ffma2(u64 a, u64 b, u64 c) {
    u64 d;
    asm("fma.rn.f32x2 %0, %1, %2, %3;" : "=l"(d) : "l"(a), "l"(b), "l"(c));
    return d;
}
__device__ __forceinline__ u64 dup2(float x) {
    u64 d;
    asm("mov.b64 %0, {%1, %1};" : "=l"(d) : "f"(x));
    return d;
}
__device__ __forceinline__ float2 unpack2(u64 v) {
    float2 r;
    asm("mov.b64 {%0, %1}, %2;" : "=f"(r.x), "=f"(r.y) : "l"(v));
    return r;
}
__device__ __forceinline__ unsigned smem_u32(const void* p) {
    unsigned a;
    asm("{ .reg .u64 t; cvta.to.shared.u64 t, %1; cvt.u32.u64 %0, t; }"
        : "=r"(a) : "l"(p));
    return a;
}
__device__ __forceinline__ void ldsm_x4(unsigned addr, unsigned& r0, unsigned& r1,
                                        unsigned& r2, unsigned& r3) {
    asm volatile("ldmatrix.sync.aligned.m8n8.x4.shared.b16 {%0,%1,%2,%3}, [%4];"
                 : "=r"(r0), "=r"(r1), "=r"(r2), "=r"(r3) : "r"(addr));
}
__device__ __forceinline__ void ldsm_x4t(unsigned addr, unsigned& r0, unsigned& r1,
                                         unsigned& r2, unsigned& r3) {
    asm volatile("ldmatrix.sync.aligned.m8n8.x4.trans.shared.b16 {%0,%1,%2,%3}, [%4];"
                 : "=r"(r0), "=r"(r1), "=r"(r2), "=r"(r3) : "r"(addr));
}
__device__ __forceinline__ void mma16816(float& d0, float& d1, float& d2, float& d3,
                                         unsigned a0, unsigned a1, unsigned a2, unsigned a3,
                                         unsigned b0, unsigned b1) {
    asm volatile(
        "mma.sync.aligned.m16n8k16.row.col.f32.f16.f16.f32 "
        "{%0,%1,%2,%3}, {%4,%5,%6,%7}, {%8,%9}, {%0,%1,%2,%3};"
        : "+f"(d0), "+f"(d1), "+f"(d2), "+f"(d3)
        : "r"(a0), "r"(a1), "r"(a2), "r"(a3), "r"(b0), "r"(b1));
}

// ---- prep: pack masked weights into g_w (float view) ----
__global__ void pixelcnn_prep(const float* __restrict__ w1, const float* __restrict__ b1,
                              const float* __restrict__ w2, const float* __restrict__ b2,
                              const float* __restrict__ w3, const float* __restrict__ b3)
{
    float* dst = reinterpret_cast<float*>(&g_w);
    const int tid = threadIdx.x;

    for (int idx = tid; idx < 24 * NCH; idx += 256) {
        int t = idx / NCH, oc = idx % NCH;
        int ky, kx;
        if (t < 21) { ky = t / 7; kx = t % 7; }
        else        { ky = 3;     kx = t - 21; }
        dst[idx] = w1[oc * 49 + ky * 7 + kx];
    }
    for (int idx = tid; idx < NCH * 5 * NCH; idx += 256) {
        int ic  = idx / (5 * NCH);
        int rem = idx % (5 * NCH);
        int t   = rem / NCH;
        int oc  = rem % NCH;
        int ky, kx;
        if (t < 3) { ky = 0; kx = t; }
        else       { ky = 1; kx = t - 3; }
        dst[384 + idx] = w2[((oc * NCH + ic) * 3 + ky) * 3 + kx];
    }
    if (tid < NCH) {
        dst[1664 + tid] = b1[tid];
        dst[1680 + tid] = b2[tid];
        dst[1696 + tid] = w3[tid];
    }
    if (tid == 0) dst[1712] = b3[0];
}

__global__ __launch_bounds__(256, 4)
void pixelcnn_fused(const float* __restrict__ x, float* __restrict__ out)
{
    __shared__ __align__(16) float   sx[XR][XC];        // 3456 B
    __shared__ __align__(16) __half  Ahi[AROWS][16];    // 19072 B (swizzled chunks)
    __shared__ __align__(16) __half  Alo[AROWS][16];    // 19072 B (swizzled chunks)
    __shared__ __align__(16) __half  Bh[5][16][16];     // 2560 B
    __shared__ __align__(16) __half  Bl[5][16][16];     // 2560 B

    const int tid  = threadIdx.x;
    const int lane = tid & 31;
    const int wid  = tid >> 5;
    const int img  = blockIdx.y;
    const int r0   = blockIdx.x * TH;
    const float* __restrict__ xim = x + img * (IMG_H * IMG_W);
    const float* cwf = reinterpret_cast<const float*>(&c_w);

    // ---- load x halo tile (zero padded) ----
    for (int idx = tid; idx < XR * XC; idx += 256) {
        int i = idx / XC, j = idx % XC;
        int gr = r0 - 4 + i;
        int gc = j - 4;
        float v = 0.0f;
        if (gr >= 0 && gr < IMG_H && gc >= 0 && gc < IMG_W)
            v = sx[0][0], v = xim[gr * IMG_W + gc];   // (dummy read removed by compiler)
        else v = 0.0f;
        sx[i][j] = v;
    }

    // ---- build conv2 B matrices (hi/lo f16) ----
    for (int idx = tid; idx < 16 * 5 * 16; idx += 256) {
        int ic  = idx / 80;
        int rem = idx % 80;
        int t   = rem / 16;
        int oc  = rem % 16;
        float v = cwf[384 + ic * 80 + t * 16 + oc];
        __half hi = __float2half_rn(v);
        __half lo = __float2half_rn(v - __half2float(hi));
        Bh[t][ic][oc] = hi;
        Bl[t][ic][oc] = lo;
    }

    // ---- zero A pad rows (594, 595) ----
    if (tid < 16) {
        int rr = 594 + (tid >> 3);
        int cc = (tid & 7) * 2;
        *reinterpret_cast<unsigned*>(&Ahi[rr][cc]) = 0u;
        *reinterpret_cast<unsigned*>(&Alo[rr][cc]) = 0u;
    }
    __syncthreads();

    // ---- conv1: all 256 threads, pixels strided by 256, all 16 oc ----
    for (int m = tid; m < 594; m += 256) {
        const int hr = m / 66;
        const int hc = m - hr * 66;
        const int grow = r0 - 1 + hr;
        const bool ok = (grow >= 0) && (hc >= 1) && (hc < 65);

        u64 acc[8];
        #pragma unroll
        for (int q = 0; q < 8; q++) acc[q] = c_w.b1[q];

        #pragma unroll
        for (int ky = 0; ky < 3; ky++) {
            #pragma unroll
            for (int kx = 0; kx < 7; kx++) {
                const int t = ky * 7 + kx;
                const u64 d = dup2(sx[hr + ky][hc + kx]);
                #pragma unroll
                for (int og = 0; og < 4; og++) {
                    ulonglong2 w = c_w.w1t[t][og];
                    acc[og * 2 + 0] = ffma2(w.x, d, acc[og * 2 + 0]);
                    acc[og * 2 + 1] = ffma2(w.y, d, acc[og * 2 + 1]);
                }
            }
        }
        #pragma unroll
        for (int kx = 0; kx < 3; kx++) {
            const int t = 21 + kx;
            const u64 d = dup2(sx[hr + 3][hc + kx]);
            #pragma unroll
            for (int og = 0; og < 4; og++) {
                ulonglong2 w = c_w.w1t[t][og];
                acc[og * 2 + 0] = ffma2(w.x, d, acc[og * 2 + 0]);
                acc[og * 2 + 1] = ffma2(w.y, d, acc[og * 2 + 1]);
            }
        }

        // relu + mask, fp16 hi/lo split, swizzled STS.128 pairs
        unsigned hiw[8], low[8];
        #pragma unroll
        for (int q = 0; q < 8; q++) {
            float2 v = unpack2(acc[q]);
            float a0 = ok ? fmaxf(v.x, 0.0f) : 0.0f;
            float a1 = ok ? fmaxf(v.y, 0.0f) : 0.0f;
            float2 vm = make_float2(a0, a1);
            __half2 hh = __float22half2_rn(vm);
            float2 back = __half22float2(hh);
            __half2 hl = __float22half2_rn(
                make_float2(vm.x - back.x, vm.y - back.y));
            hiw[q] = *reinterpret_cast<unsigned*>(&hh);
            low[q] = *reinterpret_cast<unsigned*>(&hl);
        }
        const int s0 = (m >> 2) & 1;   // swizzle bit: logical chunk c -> physical c^s0
        uint4* hiRow = reinterpret_cast<uint4*>(&Ahi[m][0]);
        uint4* loRow = reinterpret_cast<uint4*>(&Alo[m][0]);
        hiRow[s0]     = make_uint4(hiw[0], hiw[1], hiw[2], hiw[3]);  // logical chunk 0
        hiRow[1 - s0] = make_uint4(hiw[4], hiw[5], hiw[6], hiw[7]);  // logical chunk 1
        loRow[s0]     = make_uint4(low[0], low[1], low[2], low[3]);
        loRow[1 - s0] = make_uint4(low[4], low[5], low[6], low[7]);
    }
    __syncthreads();

    // ---- conv2 via mma (B fragments hoisted) + conv3 + sigmoid ----
    {
        const unsigned ahi_b = smem_u32(&Ahi[0][0]);
        const unsigned alo_b = smem_u32(&Alo[0][0]);
        const unsigned bh_b  = smem_u32(&Bh[0][0][0]);
        const unsigned bl_b  = smem_u32(&Bl[0][0][0]);

        const unsigned arow  = lane & 15;
        const unsigned akoff = (lane >> 4) * 16;   // logical k-half byte offset
        const unsigned brow  = lane & 15;
        const unsigned bnoff = (lane >> 4) * 16;

        // hoist B fragments: tile-invariant
        unsigned bh[5][4], bl[5][4];
        #pragma unroll
        for (int t = 0; t < 5; t++) {
            const unsigned bbyte = (unsigned)t * 512 + brow * 32 + bnoff;
            ldsm_x4t(bh_b + bbyte, bh[t][0], bh[t][1], bh[t][2], bh[t][3]);
            ldsm_x4t(bl_b + bbyte, bl[t][0], bl[t][1], bl[t][2], bl[t][3]);
        }

        // epilogue constants
        const int cb = (lane & 3) * 2;
        float b2c[4], w3c[4];
        #pragma unroll
        for (int j = 0; j < 2; j++) {
            b2c[j]     = cwf[1680 + cb + j];
            b2c[2 + j] = cwf[1680 + cb + 8 + j];
            w3c[j]     = cwf[1696 + cb + j];
            w3c[2 + j] = cwf[1696 + cb + 8 + j];
        }
        const float b3v = cwf[1712];

        const int shifts[5] = {0, 1, 2, 66, 67};

        for (int tile = wid; tile < 33; tile += 8) {
            const int m0 = tile * 16;
            float d0[4] = {0.f, 0.f, 0.f, 0.f};
            float d1[4] = {0.f, 0.f, 0.f, 0.f};

            #pragma unroll
            for (int t = 0; t < 5; t++) {
                const unsigned row   = (unsigned)(m0 + shifts[t]) + arow;
                const unsigned rbyte = row * 32 + (akoff ^ ((row & 4u) << 2));
                unsigned ah0, ah1, ah2, ah3, al0, al1, al2, al3;
                ldsm_x4(ahi_b + rbyte, ah0, ah1, ah2, ah3);
                ldsm_x4(alo_b + rbyte, al0, al1, al2, al3);

                mma16816(d0[0], d0[1], d0[2], d0[3], ah0, ah1, ah2, ah3, bh[t][0], bh[t][1]);
                mma16816(d1[0], d1[1], d1[2], d1[3], ah0, ah1, ah2, ah3, bh[t][2], bh[t][3]);
                mma16816(d0[0], d0[1], d0[2], d0[3], ah0, ah1, ah2, ah3, bl[t][0], bl[t][1]);
                mma16816(d1[0], d1[1], d1[2], d1[3], ah0, ah1, ah2, ah3, bl[t][2], bl[t][3]);
                mma16816(d0[0], d0[1], d0[2], d0[3], al0, al1, al2, al3, bh[t][0], bh[t][1]);
                mma16816(d1[0], d1[1], d1[2], d1[3], al0, al1, al2, al3, bh[t][2], bh[t][3]);
            }

            float zA = 0.f, zB = 0.f;
            #pragma unroll
            for (int j = 0; j < 2; j++) {
                zA += fmaxf(d0[j]     + b2c[j],     0.0f) * w3c[j];
                zA += fmaxf(d1[j]     + b2c[2 + j], 0.0f) * w3c[2 + j];
                zB += fmaxf(d0[2 + j] + b2c[j],     0.0f) * w3c[j];
                zB += fmaxf(d1[2 + j] + b2c[2 + j], 0.0f) * w3c[2 + j];
            }
            zA += __shfl_xor_sync(0xffffffffu, zA, 1);
            zA += __shfl_xor_sync(0xffffffffu, zA, 2);
            zB += __shfl_xor_sync(0xffffffffu, zB, 1);
            zB += __shfl_xor_sync(0xffffffffu, zB, 2);

            if ((lane & 3) == 0) {
                const int g = lane >> 2;
                #pragma unroll
                for (int s = 0; s < 2; s++) {
                    const int m = m0 + g + s * 8;
                    const float z = (s == 0 ? zA : zB) + b3v;
                    const int r = m / 66;
                    const int c = m - r * 66;
                    if (c < 64 && r < 8) {
                        float y = 1.0f / (1.0f + __expf(-z));
                        out[img * (IMG_H * IMG_W) + (r0 + r) * IMG_W + c] = y;
                    }
                }
            }
        }
    }
}

extern "C" void kernel_launch(void* const* d_in, const int* in_sizes, int n_in,
                              void* d_out, int out_size) {
    const float* x  = (const float*)d_in[0];
    const float* w1 = (const float*)d_in[1];
    const float* b1 = (const float*)d_in[2];
    const float* w2 = (const float*)d_in[3];
    const float* b2 = (const float*)d_in[4];
    const float* w3 = (const float*)d_in[5];
    const float* b3 = (const float*)d_in[6];
    float* out = (float*)d_out;

    cudaFuncSetAttribute(pixelcnn_fused,
                         cudaFuncAttributePreferredSharedMemoryCarveout, 100);

    pixelcnn_prep<<<1, 256>>>(w1, b1, w2, b2, w3, b3);

    void* g_addr = nullptr;
    cudaGetSymbolAddress(&g_addr, g_w);
    cudaMemcpyToSymbolAsync(c_w, g_addr, sizeof(PackedW), 0,
                            cudaMemcpyDeviceToDevice, 0);

    dim3 grid(IMG_H / TH, 1024);
    pixelcnn_fused<<<grid, 256>>>(x, out);
}